// round 10
// baseline (speedup 1.0000x reference)
#include <cuda_runtime.h>

#define N 8192
#define RANK 4
#define SCALING 2.0f   // ALPHA / RANK = 8 / 4
#define EPS 1e-5f
#define TPB 1024
#define VEC_CTAS 8               // producer CTAs; 1024 features each
#define FEAT_PER_CTA (N / VEC_CTAS)   // 1024 = one feature per thread

// Allocation-free scratch + completion flag (zero-initialized at load).
__device__ float g_scale[N];
__device__ float g_shift[N];
__device__ int   g_done;

__device__ __forceinline__ int ld_acquire_gpu(const int* p) {
    int v;
    asm volatile("ld.acquire.gpu.b32 %0, [%1];" : "=r"(v) : "l"(p) : "memory");
    return v;
}

// ---------------------------------------------------------------------------
// Single fused kernel. One CTA per row. CTAs 0..7 FIRST compute their 1024-
// feature slice of the rank-4 diag scale/shift and release-publish it, then
// do their row like everyone else. Consumers overlap the wait with their own
// x loads + reduction; the wait uses nanosleep backoff to avoid hammering L2.
// ---------------------------------------------------------------------------
__global__ __launch_bounds__(TPB) void lora_ln_fused(const float* __restrict__ x,
                                                     const float* __restrict__ sA,
                                                     const float* __restrict__ sB,
                                                     const float* __restrict__ hA,
                                                     const float* __restrict__ hB,
                                                     float* __restrict__ out) {
    const int t = threadIdx.x;
    const int lane = t & 31, warp = t >> 5;
    const int bid = blockIdx.x;

    // ---- Producer path FIRST: publish the affine vectors ASAP. ----
    if (bid < VEC_CTAS) {
        const int i = bid * FEAT_PER_CTA + t;
        float4 as = *(const float4*)(sA + i * RANK);
        float4 ah = *(const float4*)(hA + i * RANK);
        float s = as.x * sB[0 * N + i] + as.y * sB[1 * N + i]
                + as.z * sB[2 * N + i] + as.w * sB[3 * N + i];
        float h = ah.x * hB[0 * N + i] + ah.y * hB[1 * N + i]
                + ah.z * hB[2 * N + i] + ah.w * hB[3 * N + i];
        g_scale[i] = s * SCALING;
        g_shift[i] = h * SCALING;
        __syncthreads();
        if (t == 0) {
            __threadfence();              // release the slice
            atomicAdd(&g_done, 1);
        }
    }

    const size_t row_off = (size_t)bid * N;
    const float4* __restrict__ xr = (const float4*)(x + row_off);
    float4* __restrict__ yr = (float4*)(out + row_off);

    // ---- Row work: front-batched x loads. ----
    float4 v0 = xr[t];
    float4 v1 = xr[t + TPB];

    float sum = v0.x + v0.y + v0.z + v0.w + v1.x + v1.y + v1.z + v1.w;
    float sq  = v0.x * v0.x + v0.y * v0.y + v0.z * v0.z + v0.w * v0.w
              + v1.x * v1.x + v1.y * v1.y + v1.z * v1.z + v1.w * v1.w;

#pragma unroll
    for (int off = 16; off > 0; off >>= 1) {
        sum += __shfl_xor_sync(0xFFFFFFFFu, sum, off);
        sq  += __shfl_xor_sync(0xFFFFFFFFu, sq,  off);
    }

    __shared__ float2 s_part[32];
    if (lane == 0) s_part[warp] = make_float2(sum, sq);

    // ---- Dependency wait: one acquire check; backoff poll only if early.
    // (Replays pass immediately; rewritten values are byte-identical.)
    if (t == 0) {
        while (ld_acquire_gpu(&g_done) < VEC_CTAS) __nanosleep(128);
    }
    __syncthreads();   // orders s_part publish AND g_scale visibility

    // ---- Affine vectors (L1/L2-resident after the first rows per SM). ----
    const float4* __restrict__ sc = (const float4*)g_scale;
    const float4* __restrict__ sh = (const float4*)g_shift;
    float4 sc0 = sc[t];
    float4 sc1 = sc[t + TPB];
    float4 sh0 = sh[t];
    float4 sh1 = sh[t + TPB];

    // ---- Finish block reduction (every warp folds all 32 partials). ----
    float2 p = s_part[lane];
#pragma unroll
    for (int off = 16; off > 0; off >>= 1) {
        p.x += __shfl_xor_sync(0xFFFFFFFFu, p.x, off);
        p.y += __shfl_xor_sync(0xFFFFFFFFu, p.y, off);
    }
    const float mean = p.x * (1.0f / N);
    const float var  = p.y * (1.0f / N) - mean * mean;
    const float rstd = rsqrtf(var + EPS);

    // ---- Epilogue: o = v*a + b,  a = rstd*sc,  b = sh - mean*a. ----
    float4 a, b, o;
    a.x = rstd * sc0.x; a.y = rstd * sc0.y; a.z = rstd * sc0.z; a.w = rstd * sc0.w;
    b.x = sh0.x - mean * a.x; b.y = sh0.y - mean * a.y;
    b.z = sh0.z - mean * a.z; b.w = sh0.w - mean * a.w;
    o.x = v0.x * a.x + b.x; o.y = v0.y * a.y + b.y;
    o.z = v0.z * a.z + b.z; o.w = v0.w * a.w + b.w;
    yr[t] = o;

    a.x = rstd * sc1.x; a.y = rstd * sc1.y; a.z = rstd * sc1.z; a.w = rstd * sc1.w;
    b.x = sh1.x - mean * a.x; b.y = sh1.y - mean * a.y;
    b.z = sh1.z - mean * a.z; b.w = sh1.w - mean * a.w;
    o.x = v1.x * a.x + b.x; o.y = v1.y * a.y + b.y;
    o.z = v1.z * a.z + b.z; o.w = v1.w * a.w + b.w;
    yr[t + TPB] = o;
}

extern "C" void kernel_launch(void* const* d_in, const int* in_sizes, int n_in,
                              void* d_out, int out_size) {
    const float* x  = (const float*)d_in[0];
    const float* sA = (const float*)d_in[1];
    const float* sB = (const float*)d_in[2];
    const float* hA = (const float*)d_in[3];
    const float* hB = (const float*)d_in[4];
    float* out = (float*)d_out;

    const int rows = out_size / N;   // 8192
    lora_ln_fused<<<rows, TPB>>>(x, sA, sB, hA, hB, out);
}

// round 11
// speedup vs baseline: 1.2014x; 1.2014x over previous
#include <cuda_runtime.h>

#define N 8192
#define RANK 4
#define SCALING 2.0f   // ALPHA / RANK = 8 / 4
#define EPS 1e-5f
#define TPB 512
#define VPT 4          // float4 slots per thread: N / (TPB*4)

// Allocation-free scratch for the adapted affine vectors.
__device__ float g_scale[N];
__device__ float g_shift[N];

// ---------------------------------------------------------------------------
// Kernel 1: rank-4 low-rank diagonal -> per-feature scale/shift vectors.
// ---------------------------------------------------------------------------
__global__ void lora_vectors_kernel(const float* __restrict__ sA,
                                    const float* __restrict__ sB,
                                    const float* __restrict__ hA,
                                    const float* __restrict__ hB) {
    int i = blockIdx.x * blockDim.x + threadIdx.x;
    if (i >= N) return;
    float4 a_s = *(const float4*)(sA + i * RANK);
    float4 a_h = *(const float4*)(hA + i * RANK);
    float s = a_s.x * sB[0 * N + i] + a_s.y * sB[1 * N + i]
            + a_s.z * sB[2 * N + i] + a_s.w * sB[3 * N + i];
    float h = a_h.x * hB[0 * N + i] + a_h.y * hB[1 * N + i]
            + a_h.z * hB[2 * N + i] + a_h.w * hB[3 * N + i];
    g_scale[i] = s * SCALING;
    g_shift[i] = h * SCALING;
}

// ---------------------------------------------------------------------------
// Kernel 2: fused LayerNorm, one CTA (512 threads) per row.
//  - 4 front-batched streaming float4 loads per thread (MLP=4)
//  - single-barrier reduction over 16 warp partials
//  - scale/shift read in the epilogue from L1 (kept resident by .cs x loads)
//  - streaming stores
// ---------------------------------------------------------------------------
__global__ __launch_bounds__(TPB) void lora_ln_kernel(const float* __restrict__ x,
                                                      float* __restrict__ out) {
    const int t = threadIdx.x;
    const int lane = t & 31, warp = t >> 5;
    const size_t row_off = (size_t)blockIdx.x * N;
    const float4* __restrict__ xr = (const float4*)(x + row_off);
    float4* __restrict__ yr = (float4*)(out + row_off);

    // Front-batched streaming loads: slots t, t+512, t+1024, t+1536.
    float4 v[VPT];
#pragma unroll
    for (int i = 0; i < VPT; i++) v[i] = __ldcs(xr + t + i * TPB);

    float sum = 0.f, sq = 0.f;
#pragma unroll
    for (int i = 0; i < VPT; i++) {
        sum += v[i].x + v[i].y + v[i].z + v[i].w;
        sq  += v[i].x * v[i].x + v[i].y * v[i].y
             + v[i].z * v[i].z + v[i].w * v[i].w;
    }

#pragma unroll
    for (int off = 16; off > 0; off >>= 1) {
        sum += __shfl_xor_sync(0xFFFFFFFFu, sum, off);
        sq  += __shfl_xor_sync(0xFFFFFFFFu, sq,  off);
    }

    // Single barrier: 16 warp partials, then every warp folds all 16.
    __shared__ float2 s_part[16];
    if (lane == 0) s_part[warp] = make_float2(sum, sq);
    __syncthreads();

    float2 p = s_part[lane & 15];
#pragma unroll
    for (int off = 8; off > 0; off >>= 1) {
        p.x += __shfl_xor_sync(0xFFFFFFFFu, p.x, off);
        p.y += __shfl_xor_sync(0xFFFFFFFFu, p.y, off);
    }
    const float mean = p.x * (1.0f / N);
    const float var  = p.y * (1.0f / N) - mean * mean;
    const float rstd = rsqrtf(var + EPS);

    // Epilogue: o = v*a + b with a = rstd*sc, b = sh - mean*a.
    // sc/sh loads are L1 hits after the first rows on each SM.
    const float4* __restrict__ sc = (const float4*)g_scale;
    const float4* __restrict__ sh = (const float4*)g_shift;
#pragma unroll
    for (int i = 0; i < VPT; i++) {
        const int idx = t + i * TPB;
        float4 s = sc[idx];
        float4 h = sh[idx];
        float4 a, b, o;
        a.x = rstd * s.x; a.y = rstd * s.y; a.z = rstd * s.z; a.w = rstd * s.w;
        b.x = h.x - mean * a.x; b.y = h.y - mean * a.y;
        b.z = h.z - mean * a.z; b.w = h.w - mean * a.w;
        o.x = v[i].x * a.x + b.x; o.y = v[i].y * a.y + b.y;
        o.z = v[i].z * a.z + b.z; o.w = v[i].w * a.w + b.w;
        __stcs(yr + idx, o);
    }
}

extern "C" void kernel_launch(void* const* d_in, const int* in_sizes, int n_in,
                              void* d_out, int out_size) {
    const float* x  = (const float*)d_in[0];
    const float* sA = (const float*)d_in[1];
    const float* sB = (const float*)d_in[2];
    const float* hA = (const float*)d_in[3];
    const float* hB = (const float*)d_in[4];
    float* out = (float*)d_out;

    const int rows = out_size / N;   // 8192

    lora_vectors_kernel<<<N / 256, 256>>>(sA, sB, hA, hB);
    lora_ln_kernel<<<rows, TPB>>>(x, out);
}